// round 1
// baseline (speedup 1.0000x reference)
#include <cuda_runtime.h>
#include <math.h>

// ---------------- problem constants ----------------
#define BS      2
#define DMODEL  256
#define HH      28
#define NTOK    784          // 28*28
#define WWIN    7
#define MW      4            // windows per side
#define NW      16
#define WS      49
#define KTOP    8
#define NHEAD   8
#define DH      32
#define SPW     408          // KTOP*WS + NW
#define SKEY    6528         // NW * SPW
#define NCHUNK  4
#define CHUNK   1632         // SKEY / NCHUNK
#define KT      32           // key tile
#define DFF     512

// ---------------- scratch (device globals; no allocs allowed) ----------------
__device__ float g_xf  [BS*NTOK*DMODEL];
__device__ float g_q   [BS*NTOK*DMODEL];
__device__ float g_k   [BS*NTOK*DMODEL];
__device__ float g_v   [BS*NTOK*DMODEL];
__device__ float g_qm  [BS*NW*DMODEL];
__device__ float g_km  [BS*NW*DMODEL];
__device__ float g_vm  [BS*NW*DMODEL];
__device__ int   g_idx [BS*NW*KTOP];
__device__ float g_kcat[BS*SKEY*DMODEL];
__device__ float g_vcat[BS*SKEY*DMODEL];
__device__ float g_pl  [BS*NHEAD*NCHUNK*NTOK];
__device__ float g_pacc[BS*NHEAD*NCHUNK*NTOK*DH];
__device__ float g_msg [BS*NTOK*DMODEL];
__device__ float g_msg2[BS*NTOK*DMODEL];
__device__ float g_mesg[BS*NTOK*DFF];
__device__ float g_y1  [BS*NTOK*DFF];
__device__ float g_y2  [BS*NTOK*DFF];
__device__ float g_z   [BS*NTOK*DMODEL];

// ---------------- x (b,d,hw) -> xf (b,hw,d) ----------------
__global__ void k_transpose(const float* __restrict__ x, float* __restrict__ xf) {
    __shared__ float tile[32][33];
    int b  = blockIdx.z;
    int c0 = blockIdx.y * 32, n0 = blockIdx.x * 32;
    int tx = threadIdx.x, ty = threadIdx.y;   // (32, 8)
    #pragma unroll
    for (int i = 0; i < 32; i += 8) {
        int c = c0 + ty + i, n = n0 + tx;
        if (c < DMODEL && n < NTOK) tile[ty + i][tx] = x[(b * DMODEL + c) * NTOK + n];
    }
    __syncthreads();
    #pragma unroll
    for (int i = 0; i < 32; i += 8) {
        int n = n0 + ty + i, c = c0 + tx;
        if (n < NTOK && c < DMODEL) xf[(b * NTOK + n) * DMODEL + c] = tile[tx][ty + i];
    }
}

// ---------------- generic fp32 GEMM: C[M,N] = act(A[M,K] @ B[N,K]^T + bias) ----------------
// block (16,16), tile 64x64, TM=TN=4, BK=16.  act: 0=none, 1=relu
__global__ void k_gemm(const float* __restrict__ A, const float* __restrict__ B,
                       const float* __restrict__ bias, float* __restrict__ C,
                       int M, int N, int K, int act) {
    __shared__ float As[64][17];
    __shared__ float Bs[64][17];
    int bm = blockIdx.y * 64, bn = blockIdx.x * 64;
    int tx = threadIdx.x, ty = threadIdx.y;
    int tid = ty * 16 + tx;
    float acc[4][4] = {};
    for (int k0 = 0; k0 < K; k0 += 16) {
        #pragma unroll
        for (int i = 0; i < 4; i++) {
            int idx = tid + i * 256;
            int r = idx >> 4, c = idx & 15;
            int ga = bm + r;
            As[r][c] = (ga < M) ? A[ga * K + k0 + c] : 0.f;
            int gb = bn + r;
            Bs[r][c] = (gb < N) ? B[gb * K + k0 + c] : 0.f;
        }
        __syncthreads();
        #pragma unroll
        for (int kk = 0; kk < 16; kk++) {
            float a[4], bb[4];
            #pragma unroll
            for (int i = 0; i < 4; i++) a[i]  = As[ty * 4 + i][kk];
            #pragma unroll
            for (int j = 0; j < 4; j++) bb[j] = Bs[tx * 4 + j][kk];
            #pragma unroll
            for (int i = 0; i < 4; i++)
                #pragma unroll
                for (int j = 0; j < 4; j++)
                    acc[i][j] += a[i] * bb[j];
        }
        __syncthreads();
    }
    #pragma unroll
    for (int i = 0; i < 4; i++) {
        int r = bm + ty * 4 + i;
        if (r >= M) continue;
        #pragma unroll
        for (int j = 0; j < 4; j++) {
            int c = bn + tx * 4 + j;
            if (c >= N) continue;
            float vv = acc[i][j] + (bias ? bias[c] : 0.f);
            if (act == 1) vv = fmaxf(vv, 0.f);
            C[r * N + c] = vv;
        }
    }
}

// ---------------- per-window means of q,k,v ----------------
__global__ void k_means(const float* __restrict__ q, const float* __restrict__ k,
                        const float* __restrict__ v,
                        float* __restrict__ qm, float* __restrict__ km, float* __restrict__ vm) {
    int b = blockIdx.x / NW, w = blockIdx.x % NW;
    int c = threadIdx.x;
    int wr = w / MW, wc = w % MW;
    float sq = 0.f, sk = 0.f, sv = 0.f;
    for (int p = 0; p < WS; p++) {
        int pr = p / WWIN, pc = p % WWIN;
        int n  = (wr * WWIN + pr) * HH + wc * WWIN + pc;
        int o  = (b * NTOK + n) * DMODEL + c;
        sq += q[o]; sk += k[o]; sv += v[o];
    }
    int o = (b * NW + w) * DMODEL + c;
    qm[o] = sq * (1.f / 49.f);
    km[o] = sk * (1.f / 49.f);
    vm[o] = sv * (1.f / 49.f);
}

// ---------------- sim = qm @ km^T (16x16) + top-8 selection ----------------
__global__ void k_topk(const float* __restrict__ qm, const float* __restrict__ km,
                       int* __restrict__ idx) {
    int b = blockIdx.x;
    __shared__ float qs[NW][DMODEL];
    __shared__ float ks[NW][DMODEL];
    __shared__ float sim[NW][NW];
    int t = threadIdx.x;
    for (int i = 0; i < NW; i++) {
        qs[i][t] = qm[(b * NW + i) * DMODEL + t];
        ks[i][t] = km[(b * NW + i) * DMODEL + t];
    }
    __syncthreads();
    int i = t / NW, j = t % NW;
    float s = 0.f;
    for (int c = 0; c < DMODEL; c++) s += qs[i][c] * ks[j][c];
    sim[i][j] = s;
    __syncthreads();
    if (t < NW) {
        bool used[NW];
        #pragma unroll
        for (int j2 = 0; j2 < NW; j2++) used[j2] = false;
        for (int r = 0; r < KTOP; r++) {
            int best = 0; float bv = -1e30f;
            for (int j2 = 0; j2 < NW; j2++)
                if (!used[j2] && sim[t][j2] > bv) { bv = sim[t][j2]; best = j2; }
            used[best] = true;
            idx[(b * NW + t) * KTOP + r] = best;
        }
    }
}

// ---------------- gather keys/vals: (b, s=wi*408+o, d) ----------------
__global__ void k_gather(const float* __restrict__ k, const float* __restrict__ v,
                         const float* __restrict__ km, const float* __restrict__ vm,
                         const int* __restrict__ idx,
                         float* __restrict__ kcat, float* __restrict__ vcat) {
    int row = blockIdx.x;                 // 0 .. BS*SKEY-1
    int b = row / SKEY, s = row % SKEY;
    int c = threadIdx.x;
    int wi = s / SPW, o = s % SPW;
    float kv, vv;
    if (o < KTOP * WS) {
        int j = o / WS, p = o % WS;
        int sw = idx[(b * NW + wi) * KTOP + j];
        int n  = ((sw / MW) * WWIN + p / WWIN) * HH + (sw % MW) * WWIN + (p % WWIN);
        kv = k[(b * NTOK + n) * DMODEL + c];
        vv = v[(b * NTOK + n) * DMODEL + c];
    } else {
        int mi = o - KTOP * WS;
        kv = km[(b * NW + mi) * DMODEL + c];
        vv = vm[(b * NW + mi) * DMODEL + c];
    }
    kcat[(b * SKEY + s) * DMODEL + c] = kv;
    vcat[(b * SKEY + s) * DMODEL + c] = vv;
}

// ---------------- attention, split-K over key chunks ----------------
// grid (13, NHEAD, BS*NCHUNK), block 64. One query per thread.
// Scores are tiny (|s*scale| << 1), so softmax runs without the max pass.
__global__ __launch_bounds__(64) void k_attn(const float* __restrict__ qb,
                                             const float* __restrict__ kcat,
                                             const float* __restrict__ vcat,
                                             float* __restrict__ pl,
                                             float* __restrict__ pacc) {
    int qt0   = blockIdx.x * 64;
    int h     = blockIdx.y;
    int b     = blockIdx.z / NCHUNK;
    int chunk = blockIdx.z % NCHUNK;
    int t = threadIdx.x;
    int l = qt0 + t;
    int lq = (l < NTOK) ? l : 0;
    int w = lq / WS, p = lq % WS;
    int n = ((w / MW) * WWIN + p / WWIN) * HH + (w % MW) * WWIN + (p % WWIN);

    const float4* qrow = (const float4*)qb + (b * NTOK + n) * (DMODEL / 4) + h * (DH / 4);
    float4 qv[DH / 4];
    #pragma unroll
    for (int i = 0; i < DH / 4; i++) qv[i] = qrow[i];

    __shared__ float4 KV[2 * KT][DH / 4];   // rows 0..31 = K tile, 32..63 = V tile
    float lsum = 0.f;
    float acc[DH];
    #pragma unroll
    for (int d = 0; d < DH; d++) acc[d] = 0.f;
    const float scale = 0.17677669529663687f;   // 32^-0.5

    int s0 = chunk * CHUNK;
    for (int tile = 0; tile < CHUNK / KT; tile++) {
        int sbase = s0 + tile * KT;
        #pragma unroll
        for (int i = 0; i < 8; i++) {
            int f = i * 64 + t;              // 512 float4 = 64 rows x 8
            int r = f >> 3, c4 = f & 7;
            const float4* src = (r < KT) ? (const float4*)kcat : (const float4*)vcat;
            int srow = (r < KT) ? r : r - KT;
            KV[r][c4] = src[(b * SKEY + sbase + srow) * (DMODEL / 4) + h * (DH / 4) + c4];
        }
        __syncthreads();
        #pragma unroll 4
        for (int kk = 0; kk < KT; kk++) {
            float s = 0.f;
            #pragma unroll
            for (int d4 = 0; d4 < DH / 4; d4++) {
                float4 kv = KV[kk][d4];
                float4 q4 = qv[d4];
                s += q4.x * kv.x + q4.y * kv.y + q4.z * kv.z + q4.w * kv.w;
            }
            float pe = __expf(s * scale);
            lsum += pe;
            #pragma unroll
            for (int d4 = 0; d4 < DH / 4; d4++) {
                float4 vv = KV[KT + kk][d4];
                acc[d4 * 4 + 0] += pe * vv.x;
                acc[d4 * 4 + 1] += pe * vv.y;
                acc[d4 * 4 + 2] += pe * vv.z;
                acc[d4 * 4 + 3] += pe * vv.w;
            }
        }
        __syncthreads();
    }
    if (l < NTOK) {
        int pbase = ((b * NHEAD + h) * NCHUNK + chunk) * NTOK + l;
        pl[pbase] = lsum;
        #pragma unroll
        for (int d = 0; d < DH; d++) pacc[pbase * DH + d] = acc[d];
    }
}

// ---------------- combine split-K partials -> msg (b, l(window order), d) ----------------
__global__ void k_combine(const float* __restrict__ pl, const float* __restrict__ pacc,
                          float* __restrict__ msg) {
    int gq   = blockIdx.x * 8 + (threadIdx.x >> 5);   // exactly BS*NHEAD*NTOK units
    int lane = threadIdx.x & 31;
    int b = gq / (NHEAD * NTOK);
    int rem = gq % (NHEAD * NTOK);
    int h = rem / NTOK, l = rem % NTOK;
    float Ls = 0.f, o = 0.f;
    #pragma unroll
    for (int c = 0; c < NCHUNK; c++) {
        int pbase = ((b * NHEAD + h) * NCHUNK + c) * NTOK + l;
        Ls += pl[pbase];
        o  += pacc[pbase * DH + lane];
    }
    msg[(b * NTOK + l) * DMODEL + h * DH + lane] = o / Ls;
}

// ---------------- LN1 + concat: message = [xf | LN(msg2)] ----------------
__global__ void k_ln1(const float* __restrict__ msg2, const float* __restrict__ xf,
                      const float* __restrict__ g, const float* __restrict__ bta,
                      float* __restrict__ message) {
    int row = blockIdx.x;       // 0..BS*NTOK-1
    int c = threadIdx.x;        // 256
    __shared__ float red[DMODEL];
    float v = msg2[row * DMODEL + c];
    red[c] = v; __syncthreads();
    for (int s = 128; s > 0; s >>= 1) { if (c < s) red[c] += red[c + s]; __syncthreads(); }
    float mu = red[0] * (1.f / DMODEL);
    __syncthreads();
    float dv = v - mu;
    red[c] = dv * dv; __syncthreads();
    for (int s = 128; s > 0; s >>= 1) { if (c < s) red[c] += red[c + s]; __syncthreads(); }
    float var = red[0] * (1.f / DMODEL);
    float outv = dv * rsqrtf(var + 1e-5f) * g[c] + bta[c];
    message[row * DFF + DMODEL + c] = outv;
    message[row * DFF + c] = xf[row * DMODEL + c];
}

// ---------------- depthwise 3x3 conv + bias + exact gelu ----------------
__global__ void k_dwconv(const float* __restrict__ y1, const float* __restrict__ dww,
                         const float* __restrict__ dwb, float* __restrict__ y2) {
    int b = blockIdx.y;
    int nn = blockIdx.x;        // 0..783
    int c = threadIdx.x;        // 512
    int r = nn / HH, col = nn % HH;
    float s = 0.f;
    #pragma unroll
    for (int dr = -1; dr <= 1; dr++)
        #pragma unroll
        for (int dc = -1; dc <= 1; dc++) {
            int rr = r + dr, cc = col + dc;
            if (rr >= 0 && rr < HH && cc >= 0 && cc < HH)
                s += y1[(b * NTOK + rr * HH + cc) * DFF + c] * dww[c * 9 + (dr + 1) * 3 + (dc + 1)];
        }
    s += dwb[c];
    float gl = 0.5f * s * (1.f + erff(s * 0.70710678118654752f));
    y2[(b * NTOK + nn) * DFF + c] = gl;
}

// ---------------- LN2 + residual + transpose to (b,d,hw) output ----------------
__global__ void k_ln2(const float* __restrict__ z, const float* __restrict__ xf,
                      const float* __restrict__ g, const float* __restrict__ bta,
                      float* __restrict__ out) {
    int row = blockIdx.x;       // b*NTOK+n
    int c = threadIdx.x;
    __shared__ float red[DMODEL];
    float v = z[row * DMODEL + c];
    red[c] = v; __syncthreads();
    for (int s = 128; s > 0; s >>= 1) { if (c < s) red[c] += red[c + s]; __syncthreads(); }
    float mu = red[0] * (1.f / DMODEL);
    __syncthreads();
    float dv = v - mu;
    red[c] = dv * dv; __syncthreads();
    for (int s = 128; s > 0; s >>= 1) { if (c < s) red[c] += red[c + s]; __syncthreads(); }
    float var = red[0] * (1.f / DMODEL);
    float o = dv * rsqrtf(var + 1e-5f) * g[c] + bta[c] + xf[row * DMODEL + c];
    int b = row / NTOK, n = row % NTOK;
    out[(b * DMODEL + c) * NTOK + n] = o;
}

// ---------------- host launcher ----------------
static float* symf(const void* s) { void* p = nullptr; cudaGetSymbolAddress(&p, s); return (float*)p; }

extern "C" void kernel_launch(void* const* d_in, const int* in_sizes, int n_in,
                              void* d_out, int out_size) {
    const float* x    = (const float*)d_in[0];
    const float* Wq   = (const float*)d_in[1];
    const float* Wk   = (const float*)d_in[2];
    const float* Wv   = (const float*)d_in[3];
    const float* Wm   = (const float*)d_in[4];
    const float* ln1g = (const float*)d_in[5];
    const float* ln1b = (const float*)d_in[6];
    const float* fc1w = (const float*)d_in[7];
    const float* fc1b = (const float*)d_in[8];
    const float* dww  = (const float*)d_in[9];
    const float* dwb  = (const float*)d_in[10];
    const float* fc2w = (const float*)d_in[11];
    const float* fc2b = (const float*)d_in[12];
    const float* ln2g = (const float*)d_in[13];
    const float* ln2b = (const float*)d_in[14];
    float* out = (float*)d_out;

    float* xf   = symf(g_xf);
    float* q    = symf(g_q);
    float* k    = symf(g_k);
    float* v    = symf(g_v);
    float* qm   = symf(g_qm);
    float* km   = symf(g_km);
    float* vm   = symf(g_vm);
    int*   idxp = (int*)symf(g_idx);
    float* kcat = symf(g_kcat);
    float* vcat = symf(g_vcat);
    float* pl   = symf(g_pl);
    float* pacc = symf(g_pacc);
    float* msg  = symf(g_msg);
    float* msg2 = symf(g_msg2);
    float* mesg = symf(g_mesg);
    float* y1   = symf(g_y1);
    float* y2   = symf(g_y2);
    float* z    = symf(g_z);

    const int M = BS * NTOK;   // 1568

    k_transpose<<<dim3(25, 8, BS), dim3(32, 8)>>>(x, xf);

    dim3 gthr(16, 16);
    k_gemm<<<dim3(4, 25), gthr>>>(xf, Wq, nullptr, q, M, DMODEL, DMODEL, 0);
    k_gemm<<<dim3(4, 25), gthr>>>(xf, Wk, nullptr, k, M, DMODEL, DMODEL, 0);
    k_gemm<<<dim3(4, 25), gthr>>>(xf, Wv, nullptr, v, M, DMODEL, DMODEL, 0);

    k_means<<<BS * NW, DMODEL>>>(q, k, v, qm, km, vm);
    k_topk<<<BS, 256>>>(qm, km, idxp);
    k_gather<<<BS * SKEY, DMODEL>>>(k, v, km, vm, idxp, kcat, vcat);

    k_attn<<<dim3(13, NHEAD, BS * NCHUNK), 64>>>(q, kcat, vcat, pl, pacc);
    k_combine<<<(BS * NHEAD * NTOK) / 8, 256>>>(pl, pacc, msg);

    k_gemm<<<dim3(4, 25), gthr>>>(msg, Wm, nullptr, msg2, M, DMODEL, DMODEL, 0);
    k_ln1<<<M, DMODEL>>>(msg2, xf, ln1g, ln1b, mesg);

    k_gemm<<<dim3(8, 25), gthr>>>(mesg, fc1w, fc1b, y1, M, DFF, DFF, 1);
    k_dwconv<<<dim3(NTOK, BS), DFF>>>(y1, dww, dwb, y2);
    k_gemm<<<dim3(4, 25), gthr>>>(y2, fc2w, fc2b, z, M, DMODEL, DFF, 0);

    k_ln2<<<M, DMODEL>>>(z, xf, ln2g, ln2b, out);
}

// round 3
// speedup vs baseline: 2.3210x; 2.3210x over previous
#include <cuda_runtime.h>
#include <math.h>

// ---------------- problem constants ----------------
#define BS      2
#define DMODEL  256
#define HH      28
#define NTOK    784          // 28*28
#define WWIN    7
#define MW      4            // windows per side
#define NW      16
#define WS      49
#define KTOP    8
#define NHEAD   8
#define DH      32
#define DFF     512

// dedup attention: 784 token keys + 16 mean keys = 800, padded to 832
#define SKEYP   832
#define NCH2    2
#define CH2     416          // keys per chunk
#define KT      32           // key tile

// ---------------- scratch (device globals; no allocs allowed) ----------------
__device__ float g_xf  [BS*NTOK*DMODEL];
__device__ float g_q   [BS*NTOK*DMODEL];
__device__ float g_k   [BS*NTOK*DMODEL];
__device__ float g_v   [BS*NTOK*DMODEL];
__device__ float g_qm  [BS*NW*DMODEL];
__device__ float g_km  [BS*NW*DMODEL];
__device__ float g_vm  [BS*NW*DMODEL];
__device__ float g_cnt [BS*NW];
__device__ float g_pl  [BS*NHEAD*NCH2*NTOK];
__device__ float g_pacc[BS*NHEAD*NCH2*NTOK*DH];
__device__ float g_msg [BS*NTOK*DMODEL];
__device__ float g_msg2[BS*NTOK*DMODEL];
__device__ float g_mesg[BS*NTOK*DFF];
__device__ float g_y1  [BS*NTOK*DFF];
__device__ float g_y2  [BS*NTOK*DFF];
__device__ float g_z   [BS*NTOK*DMODEL];

// ---------------- x (b,d,hw) -> xf (b,hw,d) ----------------
__global__ void k_transpose(const float* __restrict__ x, float* __restrict__ xf) {
    __shared__ float tile[32][33];
    int b  = blockIdx.z;
    int c0 = blockIdx.y * 32, n0 = blockIdx.x * 32;
    int tx = threadIdx.x, ty = threadIdx.y;   // (32, 8)
    #pragma unroll
    for (int i = 0; i < 32; i += 8) {
        int c = c0 + ty + i, n = n0 + tx;
        if (c < DMODEL && n < NTOK) tile[ty + i][tx] = x[(b * DMODEL + c) * NTOK + n];
    }
    __syncthreads();
    #pragma unroll
    for (int i = 0; i < 32; i += 8) {
        int n = n0 + ty + i, c = c0 + tx;
        if (n < NTOK && c < DMODEL) xf[(b * NTOK + n) * DMODEL + c] = tile[tx][ty + i];
    }
}

// ---------------- GEMM body: C[M,N] = act(A[M,K] @ B[N,K]^T + bias) ----------------
// block (16,16). tile (TM*16) x 64. k-major smem, float4 B reads.
template<int TM>
__device__ __forceinline__ void gemm_body(const float* __restrict__ A, const float* __restrict__ B,
                                          const float* __restrict__ bias, float* __restrict__ C,
                                          int M, int N, int K, int act, int by, int bx) {
    __shared__ float As[16][TM * 16 + 4];
    __shared__ float Bs[16][68];
    int bm = by * (TM * 16), bn = bx * 64;
    int tx = threadIdx.x, ty = threadIdx.y;
    int tid = ty * 16 + tx;
    float acc[TM][4];
    #pragma unroll
    for (int i = 0; i < TM; i++)
        #pragma unroll
        for (int j = 0; j < 4; j++) acc[i][j] = 0.f;

    for (int k0 = 0; k0 < K; k0 += 16) {
        #pragma unroll
        for (int i = 0; i < TM; i++) {
            int idx = tid + i * 256;
            int kq = idx & 15, m = idx >> 4;
            int ga = bm + m;
            As[kq][m] = (ga < M) ? A[ga * K + k0 + kq] : 0.f;
        }
        #pragma unroll
        for (int i = 0; i < 4; i++) {
            int idx = tid + i * 256;
            int kq = idx & 15, n = idx >> 4;
            int gb = bn + n;
            Bs[kq][n] = (gb < N) ? B[gb * K + k0 + kq] : 0.f;
        }
        __syncthreads();
        #pragma unroll
        for (int kq = 0; kq < 16; kq++) {
            float4 b4 = *(const float4*)&Bs[kq][tx * 4];
            float a[TM];
            if (TM == 4) {
                float4 a4 = *(const float4*)&As[kq][ty * 4];
                a[0] = a4.x; a[1] = a4.y; a[2] = a4.z; a[3] = a4.w;
            } else {
                float2 a2 = *(const float2*)&As[kq][ty * 2];
                a[0] = a2.x; a[1] = a2.y;
            }
            #pragma unroll
            for (int i = 0; i < TM; i++) {
                acc[i][0] += a[i] * b4.x;
                acc[i][1] += a[i] * b4.y;
                acc[i][2] += a[i] * b4.z;
                acc[i][3] += a[i] * b4.w;
            }
        }
        __syncthreads();
    }
    #pragma unroll
    for (int i = 0; i < TM; i++) {
        int r = bm + ty * TM + i;
        if (r >= M) continue;
        #pragma unroll
        for (int j = 0; j < 4; j++) {
            int c = bn + tx * 4 + j;
            if (c >= N) continue;
            float vv = acc[i][j] + (bias ? bias[c] : 0.f);
            if (act == 1) vv = fmaxf(vv, 0.f);
            C[r * N + c] = vv;
        }
    }
}

template<int TM>
__global__ void k_gemm2(const float* __restrict__ A, const float* __restrict__ B,
                        const float* __restrict__ bias, float* __restrict__ C,
                        int M, int N, int K, int act) {
    gemm_body<TM>(A, B, bias, C, M, N, K, act, blockIdx.y, blockIdx.x);
}

// fused QKV: grid.x = 12 (3 weights x 4 col tiles), grid.y = 25
__global__ void k_qkv(const float* __restrict__ A,
                      const float* __restrict__ Wq, const float* __restrict__ Wk,
                      const float* __restrict__ Wv,
                      float* __restrict__ q, float* __restrict__ k, float* __restrict__ v) {
    int sel = blockIdx.x >> 2;
    const float* B = (sel == 0) ? Wq : (sel == 1) ? Wk : Wv;
    float* C = (sel == 0) ? q : (sel == 1) ? k : v;
    gemm_body<4>(A, B, nullptr, C, BS * NTOK, DMODEL, DMODEL, 0, blockIdx.y, blockIdx.x & 3);
}

// ---------------- per-window means of q,k,v ----------------
__global__ void k_means(const float* __restrict__ q, const float* __restrict__ k,
                        const float* __restrict__ v,
                        float* __restrict__ qm, float* __restrict__ km, float* __restrict__ vm) {
    int b = blockIdx.x / NW, w = blockIdx.x % NW;
    int c = threadIdx.x;
    int wr = w / MW, wc = w % MW;
    float sq = 0.f, sk = 0.f, sv = 0.f;
    for (int p = 0; p < WS; p++) {
        int pr = p / WWIN, pc = p % WWIN;
        int n  = (wr * WWIN + pr) * HH + wc * WWIN + pc;
        int o  = (b * NTOK + n) * DMODEL + c;
        sq += q[o]; sk += k[o]; sv += v[o];
    }
    int o = (b * NW + w) * DMODEL + c;
    qm[o] = sq * (1.f / 49.f);
    km[o] = sk * (1.f / 49.f);
    vm[o] = sv * (1.f / 49.f);
}

// ---------------- sim = qm @ km^T (16x16), top-8 select + window multiplicities ----------------
__global__ void k_topk(const float* __restrict__ qm, const float* __restrict__ km,
                       float* __restrict__ cnt) {
    int b = blockIdx.x;
    __shared__ float qs[NW][DMODEL];
    __shared__ float ks[NW][DMODEL];
    __shared__ float sim[NW][NW];
    __shared__ int scnt[NW];
    int t = threadIdx.x;
    for (int i = 0; i < NW; i++) {
        qs[i][t] = qm[(b * NW + i) * DMODEL + t];
        ks[i][t] = km[(b * NW + i) * DMODEL + t];
    }
    if (t < NW) scnt[t] = 0;
    __syncthreads();
    int i = t / NW, j = t % NW;
    float s = 0.f;
    for (int c = 0; c < DMODEL; c++) s += qs[i][c] * ks[j][c];
    sim[i][j] = s;
    __syncthreads();
    if (t < NW) {
        bool used[NW];
        #pragma unroll
        for (int j2 = 0; j2 < NW; j2++) used[j2] = false;
        for (int r = 0; r < KTOP; r++) {
            int best = 0; float bv = -1e30f;
            for (int j2 = 0; j2 < NW; j2++)
                if (!used[j2] && sim[t][j2] > bv) { bv = sim[t][j2]; best = j2; }
            used[best] = true;
            atomicAdd(&scnt[best], 1);
        }
    }
    __syncthreads();
    if (t < NW) cnt[b * NW + t] = (float)scnt[t];
}

// ---------------- dedup attention over 800 unique keys (padded to 832) ----------------
// key row r: r<784 -> token r (weight = multiplicity of its window)
//            784<=r<800 -> mean r-784 (weight 16); r>=800 -> pad (weight 0)
// grid (7, NHEAD, BS*NCH2), block 128. Scores tiny -> softmax without max pass.
__global__ __launch_bounds__(128) void k_attn(const float* __restrict__ qb,
                                              const float* __restrict__ kb,
                                              const float* __restrict__ vb,
                                              const float* __restrict__ km,
                                              const float* __restrict__ vm,
                                              const float* __restrict__ cnt,
                                              float* __restrict__ pl,
                                              float* __restrict__ pacc) {
    int qt0   = blockIdx.x * 128;
    int h     = blockIdx.y;
    int b     = blockIdx.z / NCH2;
    int chunk = blockIdx.z % NCH2;
    int t = threadIdx.x;
    int l = qt0 + t;
    int lq = (l < NTOK) ? l : 0;
    // query index l is in window order -> token n
    int w = lq / WS, p = lq % WS;
    int n = ((w / MW) * WWIN + p / WWIN) * HH + (w % MW) * WWIN + (p % WWIN);

    const float4* qrow = (const float4*)qb + (b * NTOK + n) * (DMODEL / 4) + h * (DH / 4);
    float4 qv[DH / 4];
    #pragma unroll
    for (int i = 0; i < DH / 4; i++) qv[i] = qrow[i];

    __shared__ float4 Ks[KT][DH / 4];
    __shared__ float4 Vs[KT][DH / 4];
    __shared__ float  wgt[KT];
    __shared__ float  scnt[NW];
    if (t < NW) scnt[t] = cnt[b * NW + t];

    float lsum = 0.f;
    float acc[DH];
    #pragma unroll
    for (int d = 0; d < DH; d++) acc[d] = 0.f;
    const float scale = 0.17677669529663687f;   // 32^-0.5

    int s0 = chunk * CH2;
    for (int tile = 0; tile < CH2 / KT; tile++) {
        int sbase = s0 + tile * KT;
        __syncthreads();
        // load 2*KT rows x 8 float4 = 512 float4, 128 threads -> 4 each
        #pragma unroll
        for (int i = 0; i < 4; i++) {
            int f = i * 128 + t;
            int r = f >> 3, c4 = f & 7;
            int rr = (r < KT) ? r : r - KT;
            int gr = sbase + rr;
            const float4* src;
            int rowbase;
            if (gr < NTOK) {
                src = (r < KT) ? (const float4*)kb : (const float4*)vb;
                rowbase = b * NTOK + gr;
            } else {
                int mi = gr - NTOK;
                if (mi >= NW) mi = 0;            // pad rows: weight 0, data harmless
                src = (r < KT) ? (const float4*)km : (const float4*)vm;
                rowbase = b * NW + mi;
            }
            float4 val = src[rowbase * (DMODEL / 4) + h * (DH / 4) + c4];
            if (r < KT) Ks[r][c4] = val; else Vs[r - KT][c4] = val;
        }
        if (t < KT) {
            int gr = sbase + t;
            float wv;
            if (gr < NTOK) {
                int win = (gr / (WWIN * HH)) * MW + (gr % HH) / WWIN;
                wv = scnt[win];
            } else wv = (gr < NTOK + NW) ? 16.f : 0.f;
            wgt[t] = wv;
        }
        __syncthreads();
        #pragma unroll 4
        for (int kk = 0; kk < KT; kk++) {
            float cw = wgt[kk];
            if (cw == 0.f) continue;             // uniform across block
            float s = 0.f;
            #pragma unroll
            for (int d4 = 0; d4 < DH / 4; d4++) {
                float4 kv = Ks[kk][d4];
                float4 q4 = qv[d4];
                s += q4.x * kv.x + q4.y * kv.y + q4.z * kv.z + q4.w * kv.w;
            }
            float pe = cw * __expf(s * scale);
            lsum += pe;
            #pragma unroll
            for (int d4 = 0; d4 < DH / 4; d4++) {
                float4 vv = Vs[kk][d4];
                acc[d4 * 4 + 0] += pe * vv.x;
                acc[d4 * 4 + 1] += pe * vv.y;
                acc[d4 * 4 + 2] += pe * vv.z;
                acc[d4 * 4 + 3] += pe * vv.w;
            }
        }
    }
    if (l < NTOK) {
        int pbase = ((b * NHEAD + h) * NCH2 + chunk) * NTOK + l;
        pl[pbase] = lsum;
        #pragma unroll
        for (int d = 0; d < DH; d++) pacc[pbase * DH + d] = acc[d];
    }
}

// ---------------- combine split-K partials -> msg (b, l(window order), d) ----------------
__global__ void k_combine(const float* __restrict__ pl, const float* __restrict__ pacc,
                          float* __restrict__ msg) {
    int gq   = blockIdx.x * 8 + (threadIdx.x >> 5);   // BS*NHEAD*NTOK units
    int lane = threadIdx.x & 31;
    int b = gq / (NHEAD * NTOK);
    int rem = gq % (NHEAD * NTOK);
    int h = rem / NTOK, l = rem % NTOK;
    float Ls = 0.f, o = 0.f;
    #pragma unroll
    for (int c = 0; c < NCH2; c++) {
        int pbase = ((b * NHEAD + h) * NCH2 + c) * NTOK + l;
        Ls += pl[pbase];
        o  += pacc[pbase * DH + lane];
    }
    msg[(b * NTOK + l) * DMODEL + h * DH + lane] = o / Ls;
}

// ---------------- LN1 + concat: message = [xf | LN(msg2)] ----------------
__global__ void k_ln1(const float* __restrict__ msg2, const float* __restrict__ xf,
                      const float* __restrict__ g, const float* __restrict__ bta,
                      float* __restrict__ message) {
    int row = blockIdx.x;       // 0..BS*NTOK-1
    int c = threadIdx.x;        // 256
    __shared__ float red[DMODEL];
    float v = msg2[row * DMODEL + c];
    red[c] = v; __syncthreads();
    for (int s = 128; s > 0; s >>= 1) { if (c < s) red[c] += red[c + s]; __syncthreads(); }
    float mu = red[0] * (1.f / DMODEL);
    __syncthreads();
    float dv = v - mu;
    red[c] = dv * dv; __syncthreads();
    for (int s = 128; s > 0; s >>= 1) { if (c < s) red[c] += red[c + s]; __syncthreads(); }
    float var = red[0] * (1.f / DMODEL);
    float outv = dv * rsqrtf(var + 1e-5f) * g[c] + bta[c];
    message[row * DFF + DMODEL + c] = outv;
    message[row * DFF + c] = xf[row * DMODEL + c];
}

// ---------------- depthwise 3x3 conv + bias + exact gelu ----------------
__global__ void k_dwconv(const float* __restrict__ y1, const float* __restrict__ dww,
                         const float* __restrict__ dwb, float* __restrict__ y2) {
    int b = blockIdx.y;
    int nn = blockIdx.x;        // 0..783
    int c = threadIdx.x;        // 512
    int r = nn / HH, col = nn % HH;
    float s = 0.f;
    #pragma unroll
    for (int dr = -1; dr <= 1; dr++)
        #pragma unroll
        for (int dc = -1; dc <= 1; dc++) {
            int rr = r + dr, cc = col + dc;
            if (rr >= 0 && rr < HH && cc >= 0 && cc < HH)
                s += y1[(b * NTOK + rr * HH + cc) * DFF + c] * dww[c * 9 + (dr + 1) * 3 + (dc + 1)];
        }
    s += dwb[c];
    float gl = 0.5f * s * (1.f + erff(s * 0.70710678118654752f));
    y2[(b * NTOK + nn) * DFF + c] = gl;
}

// ---------------- LN2 + residual + transpose to (b,d,hw) output ----------------
__global__ void k_ln2(const float* __restrict__ z, const float* __restrict__ xf,
                      const float* __restrict__ g, const float* __restrict__ bta,
                      float* __restrict__ out) {
    int row = blockIdx.x;       // b*NTOK+n
    int c = threadIdx.x;
    __shared__ float red[DMODEL];
    float v = z[row * DMODEL + c];
    red[c] = v; __syncthreads();
    for (int s = 128; s > 0; s >>= 1) { if (c < s) red[c] += red[c + s]; __syncthreads(); }
    float mu = red[0] * (1.f / DMODEL);
    __syncthreads();
    float dv = v - mu;
    red[c] = dv * dv; __syncthreads();
    for (int s = 128; s > 0; s >>= 1) { if (c < s) red[c] += red[c + s]; __syncthreads(); }
    float var = red[0] * (1.f / DMODEL);
    float o = dv * rsqrtf(var + 1e-5f) * g[c] + bta[c] + xf[row * DMODEL + c];
    int b = row / NTOK, n = row % NTOK;
    out[(b * DMODEL + c) * NTOK + n] = o;
}

// ---------------- host launcher ----------------
static float* symf(const void* s) { void* p = nullptr; cudaGetSymbolAddress(&p, s); return (float*)p; }

extern "C" void kernel_launch(void* const* d_in, const int* in_sizes, int n_in,
                              void* d_out, int out_size) {
    const float* x    = (const float*)d_in[0];
    const float* Wq   = (const float*)d_in[1];
    const float* Wk   = (const float*)d_in[2];
    const float* Wv   = (const float*)d_in[3];
    const float* Wm   = (const float*)d_in[4];
    const float* ln1g = (const float*)d_in[5];
    const float* ln1b = (const float*)d_in[6];
    const float* fc1w = (const float*)d_in[7];
    const float* fc1b = (const float*)d_in[8];
    const float* dww  = (const float*)d_in[9];
    const float* dwb  = (const float*)d_in[10];
    const float* fc2w = (const float*)d_in[11];
    const float* fc2b = (const float*)d_in[12];
    const float* ln2g = (const float*)d_in[13];
    const float* ln2b = (const float*)d_in[14];
    float* out = (float*)d_out;

    float* xf   = symf(g_xf);
    float* q    = symf(g_q);
    float* k    = symf(g_k);
    float* v    = symf(g_v);
    float* qm   = symf(g_qm);
    float* km   = symf(g_km);
    float* vm   = symf(g_vm);
    float* cnt  = symf(g_cnt);
    float* pl   = symf(g_pl);
    float* pacc = symf(g_pacc);
    float* msg  = symf(g_msg);
    float* msg2 = symf(g_msg2);
    float* mesg = symf(g_mesg);
    float* y1   = symf(g_y1);
    float* y2   = symf(g_y2);
    float* z    = symf(g_z);

    const int M = BS * NTOK;   // 1568
    dim3 gthr(16, 16);

    k_transpose<<<dim3(25, 8, BS), dim3(32, 8)>>>(x, xf);

    k_qkv<<<dim3(12, 25), gthr>>>(xf, Wq, Wk, Wv, q, k, v);

    k_means<<<BS * NW, DMODEL>>>(q, k, v, qm, km, vm);
    k_topk<<<BS, 256>>>(qm, km, cnt);

    k_attn<<<dim3(7, NHEAD, BS * NCH2), 128>>>(q, k, v, km, vm, cnt, pl, pacc);
    k_combine<<<(BS * NHEAD * NTOK) / 8, 256>>>(pl, pacc, msg);

    k_gemm2<2><<<dim3(4, 49), gthr>>>(msg, Wm, nullptr, msg2, M, DMODEL, DMODEL, 0);
    k_ln1<<<M, DMODEL>>>(msg2, xf, ln1g, ln1b, mesg);

    k_gemm2<4><<<dim3(8, 25), gthr>>>(mesg, fc1w, fc1b, y1, M, DFF, DFF, 1);
    k_dwconv<<<dim3(NTOK, BS), DFF>>>(y1, dww, dwb, y2);
    k_gemm2<2><<<dim3(4, 49), gthr>>>(y2, fc2w, fc2b, z, M, DMODEL, DFF, 0);

    k_ln2<<<M, DMODEL>>>(z, xf, ln2g, ln2b, out);
}

// round 5
// speedup vs baseline: 2.4705x; 1.0644x over previous
#include <cuda_runtime.h>
#include <math.h>

// ---------------- problem constants ----------------
#define BS      2
#define DMODEL  256
#define HH      28
#define NTOK    784          // 28*28
#define WWIN    7
#define MW      4            // windows per side
#define NW      16
#define WS      49
#define KTOP    8
#define NHEAD   8
#define DH      32
#define DFF     512

// dedup attention: 784 token keys + 16 mean keys = 800, padded to 832
#define NCH2    2
#define CH2     416          // keys per chunk
#define KT      32           // key tile

typedef unsigned long long ull;

// ---------------- f32x2 packed math helpers ----------------
__device__ __forceinline__ ull pack2(float a, float b) {
    ull r;
    asm("mov.b64 %0, {%1, %2};" : "=l"(r) : "f"(a), "f"(b));
    return r;
}
__device__ __forceinline__ void unpack2(ull p, float& a, float& b) {
    asm("mov.b64 {%0, %1}, %2;" : "=f"(a), "=f"(b) : "l"(p));
}
__device__ __forceinline__ void ffma2(ull& d, ull a, ull b) {
    asm("fma.rn.f32x2 %0, %1, %2, %0;" : "+l"(d) : "l"(a), "l"(b));
}

// ---------------- scratch (device globals; no allocs allowed) ----------------
__device__ float g_xf  [BS*NTOK*DMODEL];
__device__ float g_q   [BS*NTOK*DMODEL];
__device__ float g_k   [BS*NTOK*DMODEL];
__device__ float g_v   [BS*NTOK*DMODEL];
__device__ float g_qm  [BS*NW*DMODEL];
__device__ float g_km  [BS*NW*DMODEL];
__device__ float g_vm  [BS*NW*DMODEL];
__device__ float g_cnt [BS*NW];
__device__ float g_pl  [BS*NHEAD*NCH2*NTOK];
__device__ float g_pacc[BS*NHEAD*NCH2*NTOK*DH];
__device__ float g_msg [BS*NTOK*DMODEL];
__device__ float g_msg2[BS*NTOK*DMODEL];
__device__ float g_mesg[BS*NTOK*DFF];
__device__ float g_y1  [BS*NTOK*DFF];
__device__ float g_y2  [BS*NTOK*DFF];
__device__ float g_z   [BS*NTOK*DMODEL];

// ---------------- x (b,d,hw) -> xf (b,hw,d) ----------------
__global__ void k_transpose(const float* __restrict__ x, float* __restrict__ xf) {
    __shared__ float tile[32][33];
    int b  = blockIdx.z;
    int c0 = blockIdx.y * 32, n0 = blockIdx.x * 32;
    int tx = threadIdx.x, ty = threadIdx.y;   // (32, 8)
    #pragma unroll
    for (int i = 0; i < 32; i += 8) {
        int c = c0 + ty + i, n = n0 + tx;
        if (c < DMODEL && n < NTOK) tile[ty + i][tx] = x[(b * DMODEL + c) * NTOK + n];
    }
    __syncthreads();
    #pragma unroll
    for (int i = 0; i < 32; i += 8) {
        int n = n0 + ty + i, c = c0 + tx;
        if (n < NTOK && c < DMODEL) xf[(b * NTOK + n) * DMODEL + c] = tile[tx][ty + i];
    }
}

// ---------------- packed-FMA GEMM: C[M,N] = act(A[M,K] @ B[N,K]^T + bias) ----------------
// 64x64 tile, 128 threads. Each thread: 4 rows (tr*4..) x 8 cols (tc*4.., 32+tc*4..),
// accumulated as 16 packed f32x2. Requires N % 64 == 0, K % 16 == 0.
__device__ __forceinline__ void gemm3_body(const float* __restrict__ A, const float* __restrict__ B,
                                           const float* __restrict__ bias, float* __restrict__ C,
                                           int M, int N, int K, int act, int by, int bx) {
    __shared__ __align__(16) float As[16][72];
    __shared__ __align__(16) float Bs[16][72];
    int bm = by * 64, bn = bx * 64;
    int tid = threadIdx.x;          // 0..127
    int tr = tid >> 3;              // 0..15
    int tc = tid & 7;               // 0..7

    ull acc[4][4];
    #pragma unroll
    for (int i = 0; i < 4; i++)
        #pragma unroll
        for (int p = 0; p < 4; p++) acc[i][p] = 0ull;

    for (int k0 = 0; k0 < K; k0 += 16) {
        // load 64 rows x 16 k of A and B. 256 float4 each, 128 threads -> 2 each
        #pragma unroll
        for (int i = 0; i < 2; i++) {
            int f = tid + i * 128;          // 0..255
            int r = f >> 2, kq4 = f & 3;
            int ga = bm + r;
            float4 av = (ga < M) ? *(const float4*)&A[ga * K + k0 + kq4 * 4]
                                 : make_float4(0.f, 0.f, 0.f, 0.f);
            As[kq4 * 4 + 0][r] = av.x;
            As[kq4 * 4 + 1][r] = av.y;
            As[kq4 * 4 + 2][r] = av.z;
            As[kq4 * 4 + 3][r] = av.w;
            int gb = bn + r;
            float4 bv = (gb < N) ? *(const float4*)&B[gb * K + k0 + kq4 * 4]
                                 : make_float4(0.f, 0.f, 0.f, 0.f);
            Bs[kq4 * 4 + 0][r] = bv.x;
            Bs[kq4 * 4 + 1][r] = bv.y;
            Bs[kq4 * 4 + 2][r] = bv.z;
            Bs[kq4 * 4 + 3][r] = bv.w;
        }
        __syncthreads();
        #pragma unroll
        for (int kq = 0; kq < 16; kq++) {
            float4 a4 = *(const float4*)&As[kq][tr * 4];
            ulonglong2 b0 = *(const ulonglong2*)&Bs[kq][tc * 4];
            ulonglong2 b1 = *(const ulonglong2*)&Bs[kq][32 + tc * 4];
            ull pa0 = pack2(a4.x, a4.x);
            ull pa1 = pack2(a4.y, a4.y);
            ull pa2 = pack2(a4.z, a4.z);
            ull pa3 = pack2(a4.w, a4.w);
            ffma2(acc[0][0], pa0, b0.x); ffma2(acc[0][1], pa0, b0.y);
            ffma2(acc[0][2], pa0, b1.x); ffma2(acc[0][3], pa0, b1.y);
            ffma2(acc[1][0], pa1, b0.x); ffma2(acc[1][1], pa1, b0.y);
            ffma2(acc[1][2], pa1, b1.x); ffma2(acc[1][3], pa1, b1.y);
            ffma2(acc[2][0], pa2, b0.x); ffma2(acc[2][1], pa2, b0.y);
            ffma2(acc[2][2], pa2, b1.x); ffma2(acc[2][3], pa2, b1.y);
            ffma2(acc[3][0], pa3, b0.x); ffma2(acc[3][1], pa3, b0.y);
            ffma2(acc[3][2], pa3, b1.x); ffma2(acc[3][3], pa3, b1.y);
        }
        __syncthreads();
    }

    // epilogue: unpack, bias, act, store (N%64==0 so only row guard needed)
    #pragma unroll
    for (int i = 0; i < 4; i++) {
        int r = bm + tr * 4 + i;
        if (r >= M) continue;
        #pragma unroll
        for (int half = 0; half < 2; half++) {
            int c0 = bn + half * 32 + tc * 4;
            float4 o;
            unpack2(acc[i][half * 2 + 0], o.x, o.y);
            unpack2(acc[i][half * 2 + 1], o.z, o.w);
            if (bias) {
                o.x += bias[c0 + 0]; o.y += bias[c0 + 1];
                o.z += bias[c0 + 2]; o.w += bias[c0 + 3];
            }
            if (act == 1) {
                o.x = fmaxf(o.x, 0.f); o.y = fmaxf(o.y, 0.f);
                o.z = fmaxf(o.z, 0.f); o.w = fmaxf(o.w, 0.f);
            }
            *(float4*)&C[r * N + c0] = o;
        }
    }
}

__global__ __launch_bounds__(128) void k_gemm3(const float* __restrict__ A, const float* __restrict__ B,
                                               const float* __restrict__ bias, float* __restrict__ C,
                                               int M, int N, int K, int act) {
    gemm3_body(A, B, bias, C, M, N, K, act, blockIdx.y, blockIdx.x);
}

// fused QKV: grid.x = 12 (3 weights x 4 col tiles), grid.y = 25
__global__ __launch_bounds__(128) void k_qkv(const float* __restrict__ A,
                                             const float* __restrict__ Wq, const float* __restrict__ Wk,
                                             const float* __restrict__ Wv,
                                             float* __restrict__ q, float* __restrict__ k, float* __restrict__ v) {
    int sel = blockIdx.x >> 2;
    const float* B = (sel == 0) ? Wq : (sel == 1) ? Wk : Wv;
    float* C = (sel == 0) ? q : (sel == 1) ? k : v;
    gemm3_body(A, B, nullptr, C, BS * NTOK, DMODEL, DMODEL, 0, blockIdx.y, blockIdx.x & 3);
}

// ---------------- per-window means of q,k,v ----------------
__global__ void k_means(const float* __restrict__ q, const float* __restrict__ k,
                        const float* __restrict__ v,
                        float* __restrict__ qm, float* __restrict__ km, float* __restrict__ vm) {
    int b = blockIdx.x / NW, w = blockIdx.x % NW;
    int c = threadIdx.x;
    int wr = w / MW, wc = w % MW;
    float sq = 0.f, sk = 0.f, sv = 0.f;
    for (int p = 0; p < WS; p++) {
        int pr = p / WWIN, pc = p % WWIN;
        int n  = (wr * WWIN + pr) * HH + wc * WWIN + pc;
        int o  = (b * NTOK + n) * DMODEL + c;
        sq += q[o]; sk += k[o]; sv += v[o];
    }
    int o = (b * NW + w) * DMODEL + c;
    qm[o] = sq * (1.f / 49.f);
    km[o] = sk * (1.f / 49.f);
    vm[o] = sv * (1.f / 49.f);
}

// ---------------- sim = qm @ km^T (16x16), top-8 select + window multiplicities ----------------
__global__ void k_topk(const float* __restrict__ qm, const float* __restrict__ km,
                       float* __restrict__ cnt) {
    int b = blockIdx.x;
    __shared__ __align__(16) float4 qs4[NW][DMODEL / 4];
    __shared__ __align__(16) float4 ks4[NW][DMODEL / 4];
    __shared__ float sim[NW][NW];
    __shared__ int scnt[NW];
    int t = threadIdx.x;           // 256
    const float4* qm4 = (const float4*)qm;
    const float4* km4 = (const float4*)km;
    #pragma unroll
    for (int i = 0; i < 4; i++) {
        int idx = t + i * 256;     // 0..1023
        int row = idx >> 6, c = idx & 63;
        qs4[row][c] = qm4[(b * NW + row) * 64 + c];
        ks4[row][c] = km4[(b * NW + row) * 64 + c];
    }
    if (t < NW) scnt[t] = 0;
    __syncthreads();
    int i = t >> 4, j = t & 15;
    float4 s4 = make_float4(0.f, 0.f, 0.f, 0.f);
    #pragma unroll 8
    for (int c = 0; c < 64; c++) {
        float4 q4 = qs4[i][c], k4 = ks4[j][c];
        s4.x += q4.x * k4.x; s4.y += q4.y * k4.y;
        s4.z += q4.z * k4.z; s4.w += q4.w * k4.w;
    }
    sim[i][j] = (s4.x + s4.y) + (s4.z + s4.w);
    __syncthreads();
    if (t < NW) {
        float row[NW];
        #pragma unroll
        for (int j2 = 0; j2 < NW; j2++) row[j2] = sim[t][j2];
        #pragma unroll
        for (int r = 0; r < KTOP; r++) {
            int best = 0; float bv = -1e30f;
            #pragma unroll
            for (int j2 = 0; j2 < NW; j2++)
                if (row[j2] > bv) { bv = row[j2]; best = j2; }
            row[best] = -2e30f;
            atomicAdd(&scnt[best], 1);
        }
    }
    __syncthreads();
    if (t < NW) cnt[b * NW + t] = (float)scnt[t];
}

// ---------------- dedup attention over 800 unique keys (padded to 832) ----------------
// key row r: r<784 -> token r (weight = multiplicity of its window)
//            784<=r<800 -> mean r-784 (weight 16); r>=800 -> pad (weight 0)
// grid (7, NHEAD, BS*NCH2), block 128. Scores tiny -> softmax without max pass.
__global__ __launch_bounds__(128) void k_attn(const float* __restrict__ qb,
                                              const float* __restrict__ kb,
                                              const float* __restrict__ vb,
                                              const float* __restrict__ km,
                                              const float* __restrict__ vm,
                                              const float* __restrict__ cnt,
                                              float* __restrict__ pl,
                                              float* __restrict__ pacc) {
    int qt0   = blockIdx.x * 128;
    int h     = blockIdx.y;
    int b     = blockIdx.z / NCH2;
    int chunk = blockIdx.z % NCH2;
    int t = threadIdx.x;
    int l = qt0 + t;
    int lq = (l < NTOK) ? l : 0;
    // query index l is in window order -> token n
    int w = lq / WS, p = lq % WS;
    int n = ((w / MW) * WWIN + p / WWIN) * HH + (w % MW) * WWIN + (p % WWIN);

    // q row as 16 packed f32x2
    const ulonglong2* qrow = (const ulonglong2*)(qb + ((size_t)(b * NTOK + n) * DMODEL + h * DH));
    ull qp[16];
    #pragma unroll
    for (int i = 0; i < 8; i++) {
        ulonglong2 qq = qrow[i];
        qp[2 * i + 0] = qq.x;
        qp[2 * i + 1] = qq.y;
    }

    __shared__ __align__(16) float4 Ks[KT][DH / 4];
    __shared__ __align__(16) float4 Vs[KT][DH / 4];
    __shared__ float  wgt[KT];
    __shared__ float  scnt[NW];
    if (t < NW) scnt[t] = cnt[b * NW + t];

    float lsum = 0.f;
    ull acc[16];
    #pragma unroll
    for (int d = 0; d < 16; d++) acc[d] = 0ull;
    const float scale = 0.17677669529663687f;   // 32^-0.5

    int s0 = chunk * CH2;
    for (int tile = 0; tile < CH2 / KT; tile++) {
        int sbase = s0 + tile * KT;
        __syncthreads();
        // load 2*KT rows x 8 float4 = 512 float4, 128 threads -> 4 each
        #pragma unroll
        for (int i = 0; i < 4; i++) {
            int f = i * 128 + t;
            int r = f >> 3, c4 = f & 7;
            int rr = (r < KT) ? r : r - KT;
            int gr = sbase + rr;
            const float4* src;
            int rowbase;
            if (gr < NTOK) {
                src = (r < KT) ? (const float4*)kb : (const float4*)vb;
                rowbase = b * NTOK + gr;
            } else {
                int mi = gr - NTOK;
                if (mi >= NW) mi = 0;            // pad rows: weight 0, data harmless
                src = (r < KT) ? (const float4*)km : (const float4*)vm;
                rowbase = b * NW + mi;
            }
            float4 val = src[rowbase * (DMODEL / 4) + h * (DH / 4) + c4];
            if (r < KT) Ks[r][c4] = val; else Vs[r - KT][c4] = val;
        }
        if (t < KT) {
            int gr = sbase + t;
            float wv;
            if (gr < NTOK) {
                int win = (gr / (WWIN * HH)) * MW + (gr % HH) / WWIN;
                wv = scnt[win];
            } else wv = (gr < NTOK + NW) ? 16.f : 0.f;
            wgt[t] = wv;
        }
        __syncthreads();
        #pragma unroll 4
        for (int kk = 0; kk < KT; kk++) {
            float cw = wgt[kk];
            if (cw == 0.f) continue;             // uniform across block
            const ulonglong2* krow = (const ulonglong2*)&Ks[kk][0];
            ull s2 = 0ull;
            #pragma unroll
            for (int c = 0; c < 8; c++) {
                ulonglong2 kv = krow[c];
                ffma2(s2, qp[2 * c + 0], kv.x);
                ffma2(s2, qp[2 * c + 1], kv.y);
            }
            float slo, shi;
            unpack2(s2, slo, shi);
            float pe = cw * __expf((slo + shi) * scale);
            lsum += pe;
            ull pp = pack2(pe, pe);
            const ulonglong2* vrow = (const ulonglong2*)&Vs[kk][0];
            #pragma unroll
            for (int c = 0; c < 8; c++) {
                ulonglong2 vv = vrow[c];
                ffma2(acc[2 * c + 0], pp, vv.x);
                ffma2(acc[2 * c + 1], pp, vv.y);
            }
        }
    }
    if (l < NTOK) {
        int pbase = ((b * NHEAD + h) * NCH2 + chunk) * NTOK + l;
        pl[pbase] = lsum;
        #pragma unroll
        for (int d = 0; d < 16; d++) {
            float f0, f1;
            unpack2(acc[d], f0, f1);
            pacc[(size_t)pbase * DH + 2 * d + 0] = f0;
            pacc[(size_t)pbase * DH + 2 * d + 1] = f1;
        }
    }
}

// ---------------- combine split-K partials -> msg (b, l(window order), d) ----------------
__global__ void k_combine(const float* __restrict__ pl, const float* __restrict__ pacc,
                          float* __restrict__ msg) {
    int gq   = blockIdx.x * 8 + (threadIdx.x >> 5);   // BS*NHEAD*NTOK units
    int lane = threadIdx.x & 31;
    int b = gq / (NHEAD * NTOK);
    int rem = gq % (NHEAD * NTOK);
    int h = rem / NTOK, l = rem % NTOK;
    float Ls = 0.f, o = 0.f;
    #pragma unroll
    for (int c = 0; c < NCH2; c++) {
        int pbase = ((b * NHEAD + h) * NCH2 + c) * NTOK + l;
        Ls += pl[pbase];
        o  += pacc[(size_t)pbase * DH + lane];
    }
    msg[(b * NTOK + l) * DMODEL + h * DH + lane] = o / Ls;
}

// ---------------- LN1 + concat: message = [xf | LN(msg2)] ----------------
__global__ void k_ln1(const float* __restrict__ msg2, const float* __restrict__ xf,
                      const float* __restrict__ g, const float* __restrict__ bta,
                      float* __restrict__ message) {
    int row = blockIdx.x;       // 0..BS*NTOK-1
    int c = threadIdx.x;        // 256
    __shared__ float red[DMODEL];
    float v = msg2[row * DMODEL + c];
    red[c] = v; __syncthreads();
    for (int s = 128; s > 0; s >>= 1) { if (c < s) red[c] += red[c + s]; __syncthreads(); }
    float mu = red[0] * (1.f / DMODEL);
    __syncthreads();
    float dv = v - mu;
    red[c] = dv * dv; __syncthreads();
    for (int s = 128; s > 0; s >>= 1) { if (c < s) red[c] += red[c + s]; __syncthreads(); }
    float var = red[0] * (1.f / DMODEL);
    float outv = dv * rsqrtf(var + 1e-5f) * g[c] + bta[c];
    message[row * DFF + DMODEL + c] = outv;
    message[row * DFF + c] = xf[row * DMODEL + c];
}

// ---------------- depthwise 3x3 conv + bias + exact gelu ----------------
__global__ void k_dwconv(const float* __restrict__ y1, const float* __restrict__ dww,
                         const float* __restrict__ dwb, float* __restrict__ y2) {
    int b = blockIdx.y;
    int nn = blockIdx.x;        // 0..783
    int c = threadIdx.x;        // 512
    int r = nn / HH, col = nn % HH;
    float s = 0.f;
    #pragma unroll
    for (int dr = -1; dr <= 1; dr++)
        #pragma unroll
        for (int dc = -1; dc <= 1; dc++) {
            int rr = r + dr, cc = col + dc;
            if (rr >= 0 && rr < HH && cc >= 0 && cc < HH)
                s += y1[(b * NTOK + rr * HH + cc) * DFF + c] * dww[c * 9 + (dr + 1) * 3 + (dc + 1)];
        }
    s += dwb[c];
    float gl = 0.5f * s * (1.f + erff(s * 0.70710678118654752f));
    y2[(b * NTOK + nn) * DFF + c] = gl;
}

// ---------------- LN2 + residual + transpose to (b,d,hw) output ----------------
__global__ void k_ln2(const float* __restrict__ z, const float* __restrict__ xf,
                      const float* __restrict__ g, const float* __restrict__ bta,
                      float* __restrict__ out) {
    int row = blockIdx.x;       // b*NTOK+n
    int c = threadIdx.x;
    __shared__ float red[DMODEL];
    float v = z[row * DMODEL + c];
    red[c] = v; __syncthreads();
    for (int s = 128; s > 0; s >>= 1) { if (c < s) red[c] += red[c + s]; __syncthreads(); }
    float mu = red[0] * (1.f / DMODEL);
    __syncthreads();
    float dv = v - mu;
    red[c] = dv * dv; __syncthreads();
    for (int s = 128; s > 0; s >>= 1) { if (c < s) red[c] += red[c + s]; __syncthreads(); }
    float var = red[0] * (1.f / DMODEL);
    float o = dv * rsqrtf(var + 1e-5f) * g[c] + bta[c] + xf[row * DMODEL + c];
    int b = row / NTOK, n = row % NTOK;
    out[(b * DMODEL + c) * NTOK + n] = o;
}

// ---------------- host launcher ----------------
static float* symf(const void* s) { void* p = nullptr; cudaGetSymbolAddress(&p, s); return (float*)p; }

extern "C" void kernel_launch(void* const* d_in, const int* in_sizes, int n_in,
                              void* d_out, int out_size) {
    const float* x    = (const float*)d_in[0];
    const float* Wq   = (const float*)d_in[1];
    const float* Wk   = (const float*)d_in[2];
    const float* Wv   = (const float*)d_in[3];
    const float* Wm   = (const float*)d_in[4];
    const float* ln1g = (const float*)d_in[5];
    const float* ln1b = (const float*)d_in[6];
    const float* fc1w = (const float*)d_in[7];
    const float* fc1b = (const float*)d_in[8];
    const float* dww  = (const float*)d_in[9];
    const float* dwb  = (const float*)d_in[10];
    const float* fc2w = (const float*)d_in[11];
    const float* fc2b = (const float*)d_in[12];
    const float* ln2g = (const float*)d_in[13];
    const float* ln2b = (const float*)d_in[14];
    float* out = (float*)d_out;

    float* xf   = symf(g_xf);
    float* q    = symf(g_q);
    float* k    = symf(g_k);
    float* v    = symf(g_v);
    float* qm   = symf(g_qm);
    float* km   = symf(g_km);
    float* vm   = symf(g_vm);
    float* cnt  = symf(g_cnt);
    float* pl   = symf(g_pl);
    float* pacc = symf(g_pacc);
    float* msg  = symf(g_msg);
    float* msg2 = symf(g_msg2);
    float* mesg = symf(g_mesg);
    float* y1   = symf(g_y1);
    float* y2   = symf(g_y2);
    float* z    = symf(g_z);

    const int M = BS * NTOK;   // 1568

    k_transpose<<<dim3(25, 8, BS), dim3(32, 8)>>>(x, xf);

    k_qkv<<<dim3(12, 25), 128>>>(xf, Wq, Wk, Wv, q, k, v);

    k_means<<<BS * NW, DMODEL>>>(q, k, v, qm, km, vm);
    k_topk<<<BS, 256>>>(qm, km, cnt);

    k_attn<<<dim3(7, NHEAD, BS * NCH2), 128>>>(q, k, v, km, vm, cnt, pl, pacc);
    k_combine<<<(BS * NHEAD * NTOK) / 8, 256>>>(pl, pacc, msg);

    k_gemm3<<<dim3(4, 25), 128>>>(msg, Wm, nullptr, msg2, M, DMODEL, DMODEL, 0);
    k_ln1<<<M, DMODEL>>>(msg2, xf, ln1g, ln1b, mesg);

    k_gemm3<<<dim3(8, 25), 128>>>(mesg, fc1w, fc1b, y1, M, DFF, DFF, 1);
    k_dwconv<<<dim3(NTOK, BS), DFF>>>(y1, dww, dwb, y2);
    k_gemm3<<<dim3(4, 25), 128>>>(y2, fc2w, fc2b, z, M, DMODEL, DFF, 0);

    k_ln2<<<M, DMODEL>>>(z, xf, ln2g, ln2b, out);
}